// round 13
// baseline (speedup 1.0000x reference)
#include <cuda_runtime.h>
#include <math.h>
#include <stdint.h>

// Problem constants
#define T_TOK 8192          // B*S tokens
#define DDIM  1024          // model dim
#define NEXP  8             // experts
#define TOPK  2
#define HDIM  4096          // FFN hidden per expert
#define PAIRS (T_TOK * TOPK)

// ---------------- device scratch ----------------
__device__ int   g_cnt[NEXP];
__device__ int   g_fill[NEXP];
__device__ int   g_off[NEXP + 1];
__device__ int   g_topi[T_TOK * TOPK];
__device__ float g_topw[T_TOK * TOPK];
__device__ int   g_tok[PAIRS];
__device__ float g_gw[PAIRS];
__device__ __align__(16) float g_h[(size_t)PAIRS * HDIM];   // 256 MB intermediate

// ---------------- small kernels ----------------
__global__ void zero_out_kernel(float* __restrict__ out) {
    if (blockIdx.x == 0 && threadIdx.x < NEXP) {
        g_cnt[threadIdx.x] = 0;
        g_fill[threadIdx.x] = 0;
    }
    int i = blockIdx.x * blockDim.x + threadIdx.x;    // float4 idx
    const int NV = T_TOK * DDIM / 4;
    if (i < NV) ((float4*)out)[i] = make_float4(0.f, 0.f, 0.f, 0.f);
}

__global__ void router_kernel(const float* __restrict__ x,
                              const float* __restrict__ Wg,
                              const float* __restrict__ bg) {
    int warp = (blockIdx.x * blockDim.x + threadIdx.x) >> 5;
    int lane = threadIdx.x & 31;
    if (warp >= T_TOK) return;
    const float* xr = x + (size_t)warp * DDIM;

    float acc[NEXP];
#pragma unroll
    for (int e = 0; e < NEXP; e++) acc[e] = 0.f;

    for (int d = lane; d < DDIM; d += 32) {
        float xv = xr[d];
        const float4* wg = (const float4*)(Wg + (size_t)d * NEXP);
        float4 w0 = wg[0], w1 = wg[1];
        acc[0] += xv * w0.x; acc[1] += xv * w0.y;
        acc[2] += xv * w0.z; acc[3] += xv * w0.w;
        acc[4] += xv * w1.x; acc[5] += xv * w1.y;
        acc[6] += xv * w1.z; acc[7] += xv * w1.w;
    }
#pragma unroll
    for (int e = 0; e < NEXP; e++) {
#pragma unroll
        for (int o = 16; o > 0; o >>= 1)
            acc[e] += __shfl_xor_sync(0xffffffffu, acc[e], o);
    }
    if (lane == 0) {
        float logit[NEXP];
        float m = -1e30f;
#pragma unroll
        for (int e = 0; e < NEXP; e++) { logit[e] = acc[e] + bg[e]; m = fmaxf(m, logit[e]); }
        float p[NEXP], s = 0.f;
#pragma unroll
        for (int e = 0; e < NEXP; e++) { p[e] = __expf(logit[e] - m); s += p[e]; }
        float inv = 1.f / s;
#pragma unroll
        for (int e = 0; e < NEXP; e++) p[e] *= inv;
        int i1 = 0; float v1 = p[0];
#pragma unroll
        for (int e = 1; e < NEXP; e++) if (p[e] > v1) { v1 = p[e]; i1 = e; }
        int i2 = -1; float v2 = -1.f;
#pragma unroll
        for (int e = 0; e < NEXP; e++) {
            if (e == i1) continue;
            if (p[e] > v2) { v2 = p[e]; i2 = e; }
        }
        g_topi[warp * 2 + 0] = i1; g_topw[warp * 2 + 0] = v1;
        g_topi[warp * 2 + 1] = i2; g_topw[warp * 2 + 1] = v2;
        atomicAdd(&g_cnt[i1], 1);
        atomicAdd(&g_cnt[i2], 1);
    }
}

__global__ void prefix_kernel() {
    if (threadIdx.x == 0) {
        int s = 0;
        g_off[0] = 0;
        for (int e = 0; e < NEXP; e++) { s += g_cnt[e]; g_off[e + 1] = s; }
    }
}

__global__ void scatter_kernel() {
    int t = blockIdx.x * blockDim.x + threadIdx.x;
    if (t >= T_TOK) return;
#pragma unroll
    for (int k = 0; k < TOPK; k++) {
        int e = g_topi[t * 2 + k];
        int pos = atomicAdd(&g_fill[e], 1);
        int slot = g_off[e] + pos;
        g_tok[slot] = t;
        g_gw[slot] = g_topw[t * 2 + k];
    }
}

__device__ __forceinline__ float gelu_exact(float v) {
    return 0.5f * v * (1.0f + erff(v * 0.70710678118654752f));
}

// ---------------- GEMM1: h = gelu(gather(x) @ W1[e] + b1[e]) ----------------
// 128x128 tile, BK=8, 256 threads, 8x8/thread, double-buffered smem,
// 1 sync/chunk, PLUS double-buffered fragment loads across kk.
__global__ __launch_bounds__(256) void gemm1_kernel(const float* __restrict__ x,
                                                    const float* __restrict__ W1,
                                                    const float* __restrict__ b1) {
    int e = blockIdx.z;
    int n_e = g_cnt[e];
    int row0 = blockIdx.y * 128;
    if (row0 >= n_e) return;
    int col0 = blockIdx.x * 128;
    int base = g_off[e];

    __shared__ __align__(16) float As[2][8][128];
    __shared__ __align__(16) float Bs[2][8][128];

    int tid = threadIdx.x;
    int arow = tid >> 1;
    int ahalf = (tid & 1) * 4;
    int grow = row0 + arow;
    int rc = (grow < n_e) ? grow : (n_e - 1);     // clamped gather
    const float* aptr = x + (size_t)g_tok[base + rc] * DDIM + ahalf;

    int bk = tid >> 5;
    int bcol = (tid & 31) * 4;
    const float* bptr = W1 + (size_t)e * DDIM * HDIM + (size_t)bk * HDIM + col0 + bcol;

    int tx = tid & 15, ty = tid >> 4;

    float acc[8][8];
#pragma unroll
    for (int i = 0; i < 8; i++)
#pragma unroll
        for (int j = 0; j < 8; j++) acc[i][j] = 0.f;

    const int KB = DDIM / 8;

    // prologue: stage 0 -> buf0; prefetch stage 1 -> regs
    float4 aReg = *(const float4*)aptr;
    float4 bReg = *(const float4*)bptr;
    As[0][ahalf + 0][arow] = aReg.x;
    As[0][ahalf + 1][arow] = aReg.y;
    As[0][ahalf + 2][arow] = aReg.z;
    As[0][ahalf + 3][arow] = aReg.w;
    *(float4*)&Bs[0][bk][bcol] = bReg;
    aReg = *(const float4*)(aptr + 8);
    bReg = *(const float4*)(bptr + (size_t)8 * HDIM);
    __syncthreads();

    for (int kb = 0; kb < KB; kb++) {
        int buf = kb & 1;
        if (kb + 1 < KB) {
            As[buf ^ 1][ahalf + 0][arow] = aReg.x;
            As[buf ^ 1][ahalf + 1][arow] = aReg.y;
            As[buf ^ 1][ahalf + 2][arow] = aReg.z;
            As[buf ^ 1][ahalf + 3][arow] = aReg.w;
            *(float4*)&Bs[buf ^ 1][bk][bcol] = bReg;
            if (kb + 2 < KB) {
                aReg = *(const float4*)(aptr + (kb + 2) * 8);
                bReg = *(const float4*)(bptr + (size_t)(kb + 2) * 8 * HDIM);
            }
        }
        // fragment double-buffer across kk
        float af[2][8], bf[2][8];
        *(float4*)(af[0])     = *(float4*)&As[buf][0][ty * 8];
        *(float4*)(af[0] + 4) = *(float4*)&As[buf][0][ty * 8 + 4];
        *(float4*)(bf[0])     = *(float4*)&Bs[buf][0][tx * 8];
        *(float4*)(bf[0] + 4) = *(float4*)&Bs[buf][0][tx * 8 + 4];
#pragma unroll
        for (int kk = 0; kk < 8; kk++) {
            int cur = kk & 1, nxt = cur ^ 1;
            if (kk + 1 < 8) {
                *(float4*)(af[nxt])     = *(float4*)&As[buf][kk + 1][ty * 8];
                *(float4*)(af[nxt] + 4) = *(float4*)&As[buf][kk + 1][ty * 8 + 4];
                *(float4*)(bf[nxt])     = *(float4*)&Bs[buf][kk + 1][tx * 8];
                *(float4*)(bf[nxt] + 4) = *(float4*)&Bs[buf][kk + 1][tx * 8 + 4];
            }
#pragma unroll
            for (int i = 0; i < 8; i++)
#pragma unroll
                for (int j = 0; j < 8; j++) acc[i][j] += af[cur][i] * bf[cur][j];
        }
        __syncthreads();
    }

#pragma unroll
    for (int i = 0; i < 8; i++) {
        int r = row0 + ty * 8 + i;
        if (r >= n_e) break;
        size_t slot = (size_t)(base + r);
#pragma unroll
        for (int j = 0; j < 8; j += 4) {
            int n = col0 + tx * 8 + j;
            const float* bb = b1 + (size_t)e * HDIM + n;
            float4 v;
            v.x = gelu_exact(acc[i][j + 0] + bb[0]);
            v.y = gelu_exact(acc[i][j + 1] + bb[1]);
            v.z = gelu_exact(acc[i][j + 2] + bb[2]);
            v.w = gelu_exact(acc[i][j + 3] + bb[3]);
            *(float4*)&g_h[slot * HDIM + n] = v;
        }
    }
}

// ---------------- GEMM2: out[tok] += gw * (h @ W2[e] + b2[e])  (fused combine) ----------------
__global__ __launch_bounds__(256) void gemm2_kernel(const float* __restrict__ W2,
                                                    const float* __restrict__ b2,
                                                    float* __restrict__ out) {
    int e = blockIdx.z;
    int n_e = g_cnt[e];
    int row0 = blockIdx.y * 128;
    if (row0 >= n_e) return;
    int col0 = blockIdx.x * 128;
    int base = g_off[e];

    __shared__ __align__(16) float As[2][8][128];
    __shared__ __align__(16) float Bs[2][8][128];

    int tid = threadIdx.x;
    int arow = tid >> 1;
    int ahalf = (tid & 1) * 4;
    int grow = row0 + arow;
    int rc = (grow < n_e) ? grow : (n_e - 1);
    const float* aptr = g_h + (size_t)(base + rc) * HDIM + ahalf;

    int bk = tid >> 5;
    int bcol = (tid & 31) * 4;
    const float* bptr = W2 + (size_t)e * HDIM * DDIM + (size_t)bk * DDIM + col0 + bcol;

    int tx = tid & 15, ty = tid >> 4;

    float acc[8][8];
#pragma unroll
    for (int i = 0; i < 8; i++)
#pragma unroll
        for (int j = 0; j < 8; j++) acc[i][j] = 0.f;

    const int KB = HDIM / 8;

    float4 aReg = *(const float4*)aptr;
    float4 bReg = *(const float4*)bptr;
    As[0][ahalf + 0][arow] = aReg.x;
    As[0][ahalf + 1][arow] = aReg.y;
    As[0][ahalf + 2][arow] = aReg.z;
    As[0][ahalf + 3][arow] = aReg.w;
    *(float4*)&Bs[0][bk][bcol] = bReg;
    aReg = *(const float4*)(aptr + 8);
    bReg = *(const float4*)(bptr + (size_t)8 * DDIM);
    __syncthreads();

    for (int kb = 0; kb < KB; kb++) {
        int buf = kb & 1;
        if (kb + 1 < KB) {
            As[buf ^ 1][ahalf + 0][arow] = aReg.x;
            As[buf ^ 1][ahalf + 1][arow] = aReg.y;
            As[buf ^ 1][ahalf + 2][arow] = aReg.z;
            As[buf ^ 1][ahalf + 3][arow] = aReg.w;
            *(float4*)&Bs[buf ^ 1][bk][bcol] = bReg;
            if (kb + 2 < KB) {
                aReg = *(const float4*)(aptr + (kb + 2) * 8);
                bReg = *(const float4*)(bptr + (size_t)(kb + 2) * 8 * DDIM);
            }
        }
        float af[2][8], bf[2][8];
        *(float4*)(af[0])     = *(float4*)&As[buf][0][ty * 8];
        *(float4*)(af[0] + 4) = *(float4*)&As[buf][0][ty * 8 + 4];
        *(float4*)(bf[0])     = *(float4*)&Bs[buf][0][tx * 8];
        *(float4*)(bf[0] + 4) = *(float4*)&Bs[buf][0][tx * 8 + 4];
#pragma unroll
        for (int kk = 0; kk < 8; kk++) {
            int cur = kk & 1, nxt = cur ^ 1;
            if (kk + 1 < 8) {
                *(float4*)(af[nxt])     = *(float4*)&As[buf][kk + 1][ty * 8];
                *(float4*)(af[nxt] + 4) = *(float4*)&As[buf][kk + 1][ty * 8 + 4];
                *(float4*)(bf[nxt])     = *(float4*)&Bs[buf][kk + 1][tx * 8];
                *(float4*)(bf[nxt] + 4) = *(float4*)&Bs[buf][kk + 1][tx * 8 + 4];
            }
#pragma unroll
            for (int i = 0; i < 8; i++)
#pragma unroll
                for (int j = 0; j < 8; j++) acc[i][j] += af[cur][i] * bf[cur][j];
        }
        __syncthreads();
    }

    // fused combine: out[token] += gw * (acc + bias); 2 commutative adds/elem
#pragma unroll
    for (int i = 0; i < 8; i++) {
        int r = row0 + ty * 8 + i;
        if (r >= n_e) break;
        int slot = base + r;
        float gw = g_gw[slot];
        float* op = out + (size_t)g_tok[slot] * DDIM;
#pragma unroll
        for (int j = 0; j < 8; j++) {
            int n = col0 + tx * 8 + j;
            atomicAdd(op + n, gw * (acc[i][j] + b2[e * DDIM + n]));
        }
    }
}

// ---------------- launch ----------------
extern "C" void kernel_launch(void* const* d_in, const int* in_sizes, int n_in,
                              void* d_out, int out_size) {
    const float* x  = (const float*)d_in[0];
    const float* Wg = (const float*)d_in[1];
    const float* bg = (const float*)d_in[2];
    const float* W1 = (const float*)d_in[3];
    const float* b1 = (const float*)d_in[4];
    const float* W2 = (const float*)d_in[5];
    const float* b2 = (const float*)d_in[6];
    float* out = (float*)d_out;

    zero_out_kernel<<<(T_TOK * DDIM / 4 + 255) / 256, 256>>>(out);
    router_kernel<<<T_TOK / 8, 256>>>(x, Wg, bg);
    prefix_kernel<<<1, 1>>>();
    scatter_kernel<<<T_TOK / 256, 256>>>();

    dim3 g1(HDIM / 128, PAIRS / 128, NEXP);   // (32, 128, 8)
    gemm1_kernel<<<g1, 256>>>(x, W1, b1);

    dim3 g2(DDIM / 128, PAIRS / 128, NEXP);   // (8, 128, 8)
    gemm2_kernel<<<g2, 256>>>(W2, b2, out);
}

// round 14
// speedup vs baseline: 1.0620x; 1.0620x over previous
#include <cuda_runtime.h>
#include <math.h>
#include <stdint.h>

// Problem constants
#define T_TOK 8192          // B*S tokens
#define DDIM  1024          // model dim
#define NEXP  8             // experts
#define TOPK  2
#define HDIM  4096          // FFN hidden per expert
#define PAIRS (T_TOK * TOPK)
#define NSPLIT 2            // split-K factor for GEMM2
#define KSPL (HDIM / NSPLIT)

// ---------------- device scratch ----------------
__device__ int   g_cnt[NEXP];
__device__ int   g_fill[NEXP];
__device__ int   g_off[NEXP + 1];
__device__ int   g_topi[T_TOK * TOPK];
__device__ float g_topw[T_TOK * TOPK];
__device__ int   g_tok[PAIRS];
__device__ float g_gw[PAIRS];
__device__ int   g_srt[T_TOK * TOPK];                        // (t,k) -> slot
__device__ __align__(16) float g_h[(size_t)PAIRS * HDIM];    // 256 MB intermediate
__device__ __align__(16) float g_p[(size_t)NSPLIT * PAIRS * DDIM];  // 128 MB partials

// ---------------- small kernels ----------------
__global__ void zero_kernel() {
    int i = threadIdx.x;
    if (i < NEXP) { g_cnt[i] = 0; g_fill[i] = 0; }
}

__global__ void router_kernel(const float* __restrict__ x,
                              const float* __restrict__ Wg,
                              const float* __restrict__ bg) {
    int warp = (blockIdx.x * blockDim.x + threadIdx.x) >> 5;
    int lane = threadIdx.x & 31;
    if (warp >= T_TOK) return;
    const float* xr = x + (size_t)warp * DDIM;

    float acc[NEXP];
#pragma unroll
    for (int e = 0; e < NEXP; e++) acc[e] = 0.f;

    for (int d = lane; d < DDIM; d += 32) {
        float xv = xr[d];
        const float4* wg = (const float4*)(Wg + (size_t)d * NEXP);
        float4 w0 = wg[0], w1 = wg[1];
        acc[0] += xv * w0.x; acc[1] += xv * w0.y;
        acc[2] += xv * w0.z; acc[3] += xv * w0.w;
        acc[4] += xv * w1.x; acc[5] += xv * w1.y;
        acc[6] += xv * w1.z; acc[7] += xv * w1.w;
    }
#pragma unroll
    for (int e = 0; e < NEXP; e++) {
#pragma unroll
        for (int o = 16; o > 0; o >>= 1)
            acc[e] += __shfl_xor_sync(0xffffffffu, acc[e], o);
    }
    if (lane == 0) {
        float logit[NEXP];
        float m = -1e30f;
#pragma unroll
        for (int e = 0; e < NEXP; e++) { logit[e] = acc[e] + bg[e]; m = fmaxf(m, logit[e]); }
        float p[NEXP], s = 0.f;
#pragma unroll
        for (int e = 0; e < NEXP; e++) { p[e] = __expf(logit[e] - m); s += p[e]; }
        float inv = 1.f / s;
#pragma unroll
        for (int e = 0; e < NEXP; e++) p[e] *= inv;
        int i1 = 0; float v1 = p[0];
#pragma unroll
        for (int e = 1; e < NEXP; e++) if (p[e] > v1) { v1 = p[e]; i1 = e; }
        int i2 = -1; float v2 = -1.f;
#pragma unroll
        for (int e = 0; e < NEXP; e++) {
            if (e == i1) continue;
            if (p[e] > v2) { v2 = p[e]; i2 = e; }
        }
        g_topi[warp * 2 + 0] = i1; g_topw[warp * 2 + 0] = v1;
        g_topi[warp * 2 + 1] = i2; g_topw[warp * 2 + 1] = v2;
        atomicAdd(&g_cnt[i1], 1);
        atomicAdd(&g_cnt[i2], 1);
    }
}

__global__ void prefix_kernel() {
    if (threadIdx.x == 0) {
        int s = 0;
        g_off[0] = 0;
        for (int e = 0; e < NEXP; e++) { s += g_cnt[e]; g_off[e + 1] = s; }
    }
}

__global__ void scatter_kernel() {
    int t = blockIdx.x * blockDim.x + threadIdx.x;
    if (t >= T_TOK) return;
#pragma unroll
    for (int k = 0; k < TOPK; k++) {
        int e = g_topi[t * 2 + k];
        int pos = atomicAdd(&g_fill[e], 1);
        int slot = g_off[e] + pos;
        g_tok[slot] = t;
        g_gw[slot] = g_topw[t * 2 + k];
        g_srt[t * 2 + k] = slot;
    }
}

__device__ __forceinline__ float gelu_exact(float v) {
    return 0.5f * v * (1.0f + erff(v * 0.70710678118654752f));
}

// ---------------- GEMM1: h = gelu(gather(x) @ W1[e] + b1[e]) ----------------
// Exact R10 structure: 128x128 tile, BK=8, double-buffered smem, 1 sync/chunk.
__global__ __launch_bounds__(256) void gemm1_kernel(const float* __restrict__ x,
                                                    const float* __restrict__ W1,
                                                    const float* __restrict__ b1) {
    int e = blockIdx.z;
    int n_e = g_cnt[e];
    int row0 = blockIdx.y * 128;
    if (row0 >= n_e) return;
    int col0 = blockIdx.x * 128;
    int base = g_off[e];

    __shared__ __align__(16) float As[2][8][128];
    __shared__ __align__(16) float Bs[2][8][128];

    int tid = threadIdx.x;
    int arow = tid >> 1;
    int ahalf = (tid & 1) * 4;
    int grow = row0 + arow;
    int rc = (grow < n_e) ? grow : (n_e - 1);
    const float* aptr = x + (size_t)g_tok[base + rc] * DDIM + ahalf;

    int bk = tid >> 5;
    int bcol = (tid & 31) * 4;
    const float* bptr = W1 + (size_t)e * DDIM * HDIM + (size_t)bk * HDIM + col0 + bcol;

    int tx = tid & 15, ty = tid >> 4;

    float acc[8][8];
#pragma unroll
    for (int i = 0; i < 8; i++)
#pragma unroll
        for (int j = 0; j < 8; j++) acc[i][j] = 0.f;

    const int KB = DDIM / 8;

    float4 aReg = *(const float4*)aptr;
    float4 bReg = *(const float4*)bptr;
    As[0][ahalf + 0][arow] = aReg.x;
    As[0][ahalf + 1][arow] = aReg.y;
    As[0][ahalf + 2][arow] = aReg.z;
    As[0][ahalf + 3][arow] = aReg.w;
    *(float4*)&Bs[0][bk][bcol] = bReg;
    aReg = *(const float4*)(aptr + 8);
    bReg = *(const float4*)(bptr + (size_t)8 * HDIM);
    __syncthreads();

    for (int kb = 0; kb < KB; kb++) {
        int buf = kb & 1;
        if (kb + 1 < KB) {
            As[buf ^ 1][ahalf + 0][arow] = aReg.x;
            As[buf ^ 1][ahalf + 1][arow] = aReg.y;
            As[buf ^ 1][ahalf + 2][arow] = aReg.z;
            As[buf ^ 1][ahalf + 3][arow] = aReg.w;
            *(float4*)&Bs[buf ^ 1][bk][bcol] = bReg;
            if (kb + 2 < KB) {
                aReg = *(const float4*)(aptr + (kb + 2) * 8);
                bReg = *(const float4*)(bptr + (size_t)(kb + 2) * 8 * HDIM);
            }
        }
#pragma unroll
        for (int kk = 0; kk < 8; kk++) {
            float a[8], b[8];
            *(float4*)(a)     = *(float4*)&As[buf][kk][ty * 8];
            *(float4*)(a + 4) = *(float4*)&As[buf][kk][ty * 8 + 4];
            *(float4*)(b)     = *(float4*)&Bs[buf][kk][tx * 8];
            *(float4*)(b + 4) = *(float4*)&Bs[buf][kk][tx * 8 + 4];
#pragma unroll
            for (int i = 0; i < 8; i++)
#pragma unroll
                for (int j = 0; j < 8; j++) acc[i][j] += a[i] * b[j];
        }
        __syncthreads();
    }

#pragma unroll
    for (int i = 0; i < 8; i++) {
        int r = row0 + ty * 8 + i;
        if (r >= n_e) break;
        size_t slot = (size_t)(base + r);
#pragma unroll
        for (int j = 0; j < 8; j += 4) {
            int n = col0 + tx * 8 + j;
            const float* bb = b1 + (size_t)e * HDIM + n;
            float4 v;
            v.x = gelu_exact(acc[i][j + 0] + bb[0]);
            v.y = gelu_exact(acc[i][j + 1] + bb[1]);
            v.z = gelu_exact(acc[i][j + 2] + bb[2]);
            v.w = gelu_exact(acc[i][j + 3] + bb[3]);
            *(float4*)&g_h[slot * HDIM + n] = v;
        }
    }
}

// ---------------- GEMM2 split-K: p[s][slot] = h[:, sK:(s+1)K] @ W2[e][sK:(s+1)K, :] ----------------
__global__ __launch_bounds__(256) void gemm2_kernel(const float* __restrict__ W2) {
    int z = blockIdx.z;
    int e = z >> 1;            // NSPLIT = 2
    int sp = z & 1;
    int n_e = g_cnt[e];
    int row0 = blockIdx.y * 128;
    if (row0 >= n_e) return;
    int col0 = blockIdx.x * 128;
    int base = g_off[e];
    int k0g = sp * KSPL;

    __shared__ __align__(16) float As[2][8][128];
    __shared__ __align__(16) float Bs[2][8][128];

    int tid = threadIdx.x;
    int arow = tid >> 1;
    int ahalf = (tid & 1) * 4;
    int grow = row0 + arow;
    int rc = (grow < n_e) ? grow : (n_e - 1);
    const float* aptr = g_h + (size_t)(base + rc) * HDIM + k0g + ahalf;

    int bk = tid >> 5;
    int bcol = (tid & 31) * 4;
    const float* bptr = W2 + ((size_t)e * HDIM + k0g + bk) * DDIM + col0 + bcol;

    int tx = tid & 15, ty = tid >> 4;

    float acc[8][8];
#pragma unroll
    for (int i = 0; i < 8; i++)
#pragma unroll
        for (int j = 0; j < 8; j++) acc[i][j] = 0.f;

    const int KB = KSPL / 8;

    float4 aReg = *(const float4*)aptr;
    float4 bReg = *(const float4*)bptr;
    As[0][ahalf + 0][arow] = aReg.x;
    As[0][ahalf + 1][arow] = aReg.y;
    As[0][ahalf + 2][arow] = aReg.z;
    As[0][ahalf + 3][arow] = aReg.w;
    *(float4*)&Bs[0][bk][bcol] = bReg;
    aReg = *(const float4*)(aptr + 8);
    bReg = *(const float4*)(bptr + (size_t)8 * DDIM);
    __syncthreads();

    for (int kb = 0; kb < KB; kb++) {
        int buf = kb & 1;
        if (kb + 1 < KB) {
            As[buf ^ 1][ahalf + 0][arow] = aReg.x;
            As[buf ^ 1][ahalf + 1][arow] = aReg.y;
            As[buf ^ 1][ahalf + 2][arow] = aReg.z;
            As[buf ^ 1][ahalf + 3][arow] = aReg.w;
            *(float4*)&Bs[buf ^ 1][bk][bcol] = bReg;
            if (kb + 2 < KB) {
                aReg = *(const float4*)(aptr + (kb + 2) * 8);
                bReg = *(const float4*)(bptr + (size_t)(kb + 2) * 8 * DDIM);
            }
        }
#pragma unroll
        for (int kk = 0; kk < 8; kk++) {
            float a[8], b[8];
            *(float4*)(a)     = *(float4*)&As[buf][kk][ty * 8];
            *(float4*)(a + 4) = *(float4*)&As[buf][kk][ty * 8 + 4];
            *(float4*)(b)     = *(float4*)&Bs[buf][kk][tx * 8];
            *(float4*)(b + 4) = *(float4*)&Bs[buf][kk][tx * 8 + 4];
#pragma unroll
            for (int i = 0; i < 8; i++)
#pragma unroll
                for (int j = 0; j < 8; j++) acc[i][j] += a[i] * b[j];
        }
        __syncthreads();
    }

    float* pp = g_p + (size_t)sp * PAIRS * DDIM;
#pragma unroll
    for (int i = 0; i < 8; i++) {
        int r = row0 + ty * 8 + i;
        if (r >= n_e) break;
        size_t slot = (size_t)(base + r);
#pragma unroll
        for (int j = 0; j < 8; j += 4) {
            int n = col0 + tx * 8 + j;
            *(float4*)&pp[slot * DDIM + n] = *(float4*)&acc[i][j];
        }
    }
}

// ---------------- reduce: out[t] = sum_k gw * (sum_s p[s][slot] + b2[e]) ----------------
__global__ void reduce_kernel(const float* __restrict__ b2, float* __restrict__ out) {
    int i = blockIdx.x * blockDim.x + threadIdx.x;   // float4 index
    const int NV = T_TOK * DDIM / 4;
    if (i >= NV) return;
    int t = i / (DDIM / 4);
    int d4 = i % (DDIM / 4);
    const float4* p0 = (const float4*)g_p;
    const float4* p1 = (const float4*)(g_p + (size_t)PAIRS * DDIM);
    float4 r = make_float4(0.f, 0.f, 0.f, 0.f);
#pragma unroll
    for (int k = 0; k < TOPK; k++) {
        int slot = g_srt[t * 2 + k];
        int e = g_topi[t * 2 + k];
        float gw = g_topw[t * 2 + k];
        size_t idx = (size_t)slot * (DDIM / 4) + d4;
        float4 a = p0[idx];
        float4 b = p1[idx];
        const float4 bb = ((const float4*)b2)[e * (DDIM / 4) + d4];
        r.x += gw * (a.x + b.x + bb.x);
        r.y += gw * (a.y + b.y + bb.y);
        r.z += gw * (a.z + b.z + bb.z);
        r.w += gw * (a.w + b.w + bb.w);
    }
    ((float4*)out)[i] = r;
}

// ---------------- launch ----------------
extern "C" void kernel_launch(void* const* d_in, const int* in_sizes, int n_in,
                              void* d_out, int out_size) {
    const float* x  = (const float*)d_in[0];
    const float* Wg = (const float*)d_in[1];
    const float* bg = (const float*)d_in[2];
    const float* W1 = (const float*)d_in[3];
    const float* b1 = (const float*)d_in[4];
    const float* W2 = (const float*)d_in[5];
    const float* b2 = (const float*)d_in[6];
    float* out = (float*)d_out;

    zero_kernel<<<1, 32>>>();
    router_kernel<<<T_TOK / 8, 256>>>(x, Wg, bg);
    prefix_kernel<<<1, 1>>>();
    scatter_kernel<<<T_TOK / 256, 256>>>();

    // max n_e per expert is T_TOK = 8192 -> 64 row tiles suffice
    dim3 g1(HDIM / 128, T_TOK / 128, NEXP);          // (32, 64, 8)
    gemm1_kernel<<<g1, 256>>>(x, W1, b1);

    dim3 g2(DDIM / 128, T_TOK / 128, NEXP * NSPLIT); // (8, 64, 16)
    gemm2_kernel<<<g2, 256>>>(W2);

    reduce_kernel<<<(T_TOK * DDIM / 4 + 255) / 256, 256>>>(b2, out);
}

// round 15
// speedup vs baseline: 1.1705x; 1.1021x over previous
#include <cuda_runtime.h>
#include <math.h>
#include <stdint.h>

// Problem constants
#define T_TOK 8192          // B*S tokens
#define DDIM  1024          // model dim
#define NEXP  8             // experts
#define TOPK  2
#define HDIM  4096          // FFN hidden per expert
#define PAIRS (T_TOK * TOPK)
#define NSPLIT 2            // split-K factor for GEMM2
#define KSPL (HDIM / NSPLIT)

// ---------------- device scratch ----------------
__device__ int   g_cnt[NEXP];
__device__ int   g_fill[NEXP];
__device__ int   g_off[NEXP + 1];
__device__ int   g_topi[T_TOK * TOPK];
__device__ float g_topw[T_TOK * TOPK];
__device__ int   g_tok[PAIRS];
__device__ float g_gw[PAIRS];
__device__ int   g_srt[T_TOK * TOPK];                        // (t,k) -> slot
__device__ __align__(16) float g_h[(size_t)PAIRS * HDIM];    // 256 MB intermediate
__device__ __align__(16) float g_p[(size_t)NSPLIT * PAIRS * DDIM];  // 128 MB partials

// ---------------- small kernels ----------------
__global__ void zero_kernel() {
    int i = threadIdx.x;
    if (i < NEXP) { g_cnt[i] = 0; g_fill[i] = 0; }
}

__global__ void router_kernel(const float* __restrict__ x,
                              const float* __restrict__ Wg,
                              const float* __restrict__ bg) {
    int warp = (blockIdx.x * blockDim.x + threadIdx.x) >> 5;
    int lane = threadIdx.x & 31;
    if (warp >= T_TOK) return;
    const float* xr = x + (size_t)warp * DDIM;

    float acc[NEXP];
#pragma unroll
    for (int e = 0; e < NEXP; e++) acc[e] = 0.f;

    for (int d = lane; d < DDIM; d += 32) {
        float xv = xr[d];
        const float4* wg = (const float4*)(Wg + (size_t)d * NEXP);
        float4 w0 = wg[0], w1 = wg[1];
        acc[0] += xv * w0.x; acc[1] += xv * w0.y;
        acc[2] += xv * w0.z; acc[3] += xv * w0.w;
        acc[4] += xv * w1.x; acc[5] += xv * w1.y;
        acc[6] += xv * w1.z; acc[7] += xv * w1.w;
    }
#pragma unroll
    for (int e = 0; e < NEXP; e++) {
#pragma unroll
        for (int o = 16; o > 0; o >>= 1)
            acc[e] += __shfl_xor_sync(0xffffffffu, acc[e], o);
    }
    if (lane == 0) {
        float logit[NEXP];
        float m = -1e30f;
#pragma unroll
        for (int e = 0; e < NEXP; e++) { logit[e] = acc[e] + bg[e]; m = fmaxf(m, logit[e]); }
        float p[NEXP], s = 0.f;
#pragma unroll
        for (int e = 0; e < NEXP; e++) { p[e] = __expf(logit[e] - m); s += p[e]; }
        float inv = 1.f / s;
#pragma unroll
        for (int e = 0; e < NEXP; e++) p[e] *= inv;
        int i1 = 0; float v1 = p[0];
#pragma unroll
        for (int e = 1; e < NEXP; e++) if (p[e] > v1) { v1 = p[e]; i1 = e; }
        int i2 = -1; float v2 = -1.f;
#pragma unroll
        for (int e = 0; e < NEXP; e++) {
            if (e == i1) continue;
            if (p[e] > v2) { v2 = p[e]; i2 = e; }
        }
        g_topi[warp * 2 + 0] = i1; g_topw[warp * 2 + 0] = v1;
        g_topi[warp * 2 + 1] = i2; g_topw[warp * 2 + 1] = v2;
        atomicAdd(&g_cnt[i1], 1);
        atomicAdd(&g_cnt[i2], 1);
    }
}

__global__ void prefix_kernel() {
    if (threadIdx.x == 0) {
        int s = 0;
        g_off[0] = 0;
        for (int e = 0; e < NEXP; e++) { s += g_cnt[e]; g_off[e + 1] = s; }
    }
}

__global__ void scatter_kernel() {
    int t = blockIdx.x * blockDim.x + threadIdx.x;
    if (t >= T_TOK) return;
#pragma unroll
    for (int k = 0; k < TOPK; k++) {
        int e = g_topi[t * 2 + k];
        int pos = atomicAdd(&g_fill[e], 1);
        int slot = g_off[e] + pos;
        g_tok[slot] = t;
        g_gw[slot] = g_topw[t * 2 + k];
        g_srt[t * 2 + k] = slot;
    }
}

__device__ __forceinline__ float gelu_exact(float v) {
    return 0.5f * v * (1.0f + erff(v * 0.70710678118654752f));
}

// ---------------- GEMM1: h = gelu(gather(x) @ W1[e] + b1[e]) ----------------
// CTA tile 128(M) x 256(N), BK=8, 256 threads, 8x16/thread.
// B-fragment columns strided (tx*4 + q*64) -> conflict-free LDS.128.
__global__ __launch_bounds__(256) void gemm1_kernel(const float* __restrict__ x,
                                                    const float* __restrict__ W1,
                                                    const float* __restrict__ b1) {
    int e = blockIdx.z;
    int n_e = g_cnt[e];
    int row0 = blockIdx.y * 128;
    if (row0 >= n_e) return;
    int col0 = blockIdx.x * 256;
    int base = g_off[e];

    __shared__ __align__(16) float As[2][8][128];   // 8 KB
    __shared__ __align__(16) float Bs[2][8][256];   // 16 KB

    int tid = threadIdx.x;
    int arow = tid >> 1;
    int ahalf = (tid & 1) * 4;
    int grow = row0 + arow;
    int rc = (grow < n_e) ? grow : (n_e - 1);
    const float* aptr = x + (size_t)g_tok[base + rc] * DDIM + ahalf;

    int bk = tid >> 5;
    int bcol = (tid & 31) * 4;
    const float* bptr = W1 + (size_t)e * DDIM * HDIM + (size_t)bk * HDIM + col0 + bcol;

    int tx = tid & 15, ty = tid >> 4;

    float acc[8][16];
#pragma unroll
    for (int i = 0; i < 8; i++)
#pragma unroll
        for (int j = 0; j < 16; j++) acc[i][j] = 0.f;

    const int KB = DDIM / 8;

    float4 aReg = *(const float4*)aptr;
    float4 bReg0 = *(const float4*)bptr;
    float4 bReg1 = *(const float4*)(bptr + 128);
    As[0][ahalf + 0][arow] = aReg.x;
    As[0][ahalf + 1][arow] = aReg.y;
    As[0][ahalf + 2][arow] = aReg.z;
    As[0][ahalf + 3][arow] = aReg.w;
    *(float4*)&Bs[0][bk][bcol] = bReg0;
    *(float4*)&Bs[0][bk][bcol + 128] = bReg1;
    aReg  = *(const float4*)(aptr + 8);
    bReg0 = *(const float4*)(bptr + (size_t)8 * HDIM);
    bReg1 = *(const float4*)(bptr + (size_t)8 * HDIM + 128);
    __syncthreads();

    for (int kb = 0; kb < KB; kb++) {
        int buf = kb & 1;
        if (kb + 1 < KB) {
            As[buf ^ 1][ahalf + 0][arow] = aReg.x;
            As[buf ^ 1][ahalf + 1][arow] = aReg.y;
            As[buf ^ 1][ahalf + 2][arow] = aReg.z;
            As[buf ^ 1][ahalf + 3][arow] = aReg.w;
            *(float4*)&Bs[buf ^ 1][bk][bcol] = bReg0;
            *(float4*)&Bs[buf ^ 1][bk][bcol + 128] = bReg1;
            if (kb + 2 < KB) {
                aReg  = *(const float4*)(aptr + (kb + 2) * 8);
                bReg0 = *(const float4*)(bptr + (size_t)(kb + 2) * 8 * HDIM);
                bReg1 = *(const float4*)(bptr + (size_t)(kb + 2) * 8 * HDIM + 128);
            }
        }
#pragma unroll
        for (int kk = 0; kk < 8; kk++) {
            float a[8], b[16];
            *(float4*)(a)     = *(float4*)&As[buf][kk][ty * 8];
            *(float4*)(a + 4) = *(float4*)&As[buf][kk][ty * 8 + 4];
#pragma unroll
            for (int q = 0; q < 4; q++)
                *(float4*)(b + q * 4) = *(float4*)&Bs[buf][kk][tx * 4 + q * 64];
#pragma unroll
            for (int i = 0; i < 8; i++)
#pragma unroll
                for (int j = 0; j < 16; j++) acc[i][j] += a[i] * b[j];
        }
        __syncthreads();
    }

#pragma unroll
    for (int i = 0; i < 8; i++) {
        int r = row0 + ty * 8 + i;
        if (r >= n_e) break;
        size_t slot = (size_t)(base + r);
#pragma unroll
        for (int q = 0; q < 4; q++) {
            int n = col0 + tx * 4 + q * 64;
            const float* bb = b1 + (size_t)e * HDIM + n;
            float4 v;
            v.x = gelu_exact(acc[i][q * 4 + 0] + bb[0]);
            v.y = gelu_exact(acc[i][q * 4 + 1] + bb[1]);
            v.z = gelu_exact(acc[i][q * 4 + 2] + bb[2]);
            v.w = gelu_exact(acc[i][q * 4 + 3] + bb[3]);
            *(float4*)&g_h[slot * HDIM + n] = v;
        }
    }
}

// ---------------- GEMM2 split-K: p[s][slot] = h[:, sK:(s+1)K] @ W2[e][sK:(s+1)K, :] ----------------
__global__ __launch_bounds__(256) void gemm2_kernel(const float* __restrict__ W2) {
    int z = blockIdx.z;
    int e = z >> 1;            // NSPLIT = 2
    int sp = z & 1;
    int n_e = g_cnt[e];
    int row0 = blockIdx.y * 128;
    if (row0 >= n_e) return;
    int col0 = blockIdx.x * 256;
    int base = g_off[e];
    int k0g = sp * KSPL;

    __shared__ __align__(16) float As[2][8][128];
    __shared__ __align__(16) float Bs[2][8][256];

    int tid = threadIdx.x;
    int arow = tid >> 1;
    int ahalf = (tid & 1) * 4;
    int grow = row0 + arow;
    int rc = (grow < n_e) ? grow : (n_e - 1);
    const float* aptr = g_h + (size_t)(base + rc) * HDIM + k0g + ahalf;

    int bk = tid >> 5;
    int bcol = (tid & 31) * 4;
    const float* bptr = W2 + ((size_t)e * HDIM + k0g + bk) * DDIM + col0 + bcol;

    int tx = tid & 15, ty = tid >> 4;

    float acc[8][16];
#pragma unroll
    for (int i = 0; i < 8; i++)
#pragma unroll
        for (int j = 0; j < 16; j++) acc[i][j] = 0.f;

    const int KB = KSPL / 8;

    float4 aReg = *(const float4*)aptr;
    float4 bReg0 = *(const float4*)bptr;
    float4 bReg1 = *(const float4*)(bptr + 128);
    As[0][ahalf + 0][arow] = aReg.x;
    As[0][ahalf + 1][arow] = aReg.y;
    As[0][ahalf + 2][arow] = aReg.z;
    As[0][ahalf + 3][arow] = aReg.w;
    *(float4*)&Bs[0][bk][bcol] = bReg0;
    *(float4*)&Bs[0][bk][bcol + 128] = bReg1;
    aReg  = *(const float4*)(aptr + 8);
    bReg0 = *(const float4*)(bptr + (size_t)8 * DDIM);
    bReg1 = *(const float4*)(bptr + (size_t)8 * DDIM + 128);
    __syncthreads();

    for (int kb = 0; kb < KB; kb++) {
        int buf = kb & 1;
        if (kb + 1 < KB) {
            As[buf ^ 1][ahalf + 0][arow] = aReg.x;
            As[buf ^ 1][ahalf + 1][arow] = aReg.y;
            As[buf ^ 1][ahalf + 2][arow] = aReg.z;
            As[buf ^ 1][ahalf + 3][arow] = aReg.w;
            *(float4*)&Bs[buf ^ 1][bk][bcol] = bReg0;
            *(float4*)&Bs[buf ^ 1][bk][bcol + 128] = bReg1;
            if (kb + 2 < KB) {
                aReg  = *(const float4*)(aptr + (kb + 2) * 8);
                bReg0 = *(const float4*)(bptr + (size_t)(kb + 2) * 8 * DDIM);
                bReg1 = *(const float4*)(bptr + (size_t)(kb + 2) * 8 * DDIM + 128);
            }
        }
#pragma unroll
        for (int kk = 0; kk < 8; kk++) {
            float a[8], b[16];
            *(float4*)(a)     = *(float4*)&As[buf][kk][ty * 8];
            *(float4*)(a + 4) = *(float4*)&As[buf][kk][ty * 8 + 4];
#pragma unroll
            for (int q = 0; q < 4; q++)
                *(float4*)(b + q * 4) = *(float4*)&Bs[buf][kk][tx * 4 + q * 64];
#pragma unroll
            for (int i = 0; i < 8; i++)
#pragma unroll
                for (int j = 0; j < 16; j++) acc[i][j] += a[i] * b[j];
        }
        __syncthreads();
    }

    float* pp = g_p + (size_t)sp * PAIRS * DDIM;
#pragma unroll
    for (int i = 0; i < 8; i++) {
        int r = row0 + ty * 8 + i;
        if (r >= n_e) break;
        size_t slot = (size_t)(base + r);
#pragma unroll
        for (int q = 0; q < 4; q++) {
            int n = col0 + tx * 4 + q * 64;
            *(float4*)&pp[slot * DDIM + n] = *(float4*)&acc[i][q * 4];
        }
    }
}

// ---------------- reduce: out[t] = sum_k gw * (sum_s p[s][slot] + b2[e]) ----------------
__global__ void reduce_kernel(const float* __restrict__ b2, float* __restrict__ out) {
    int i = blockIdx.x * blockDim.x + threadIdx.x;   // float4 index
    const int NV = T_TOK * DDIM / 4;
    if (i >= NV) return;
    int t = i / (DDIM / 4);
    int d4 = i % (DDIM / 4);
    const float4* p0 = (const float4*)g_p;
    const float4* p1 = (const float4*)(g_p + (size_t)PAIRS * DDIM);
    float4 r = make_float4(0.f, 0.f, 0.f, 0.f);
#pragma unroll
    for (int k = 0; k < TOPK; k++) {
        int slot = g_srt[t * 2 + k];
        int e = g_topi[t * 2 + k];
        float gw = g_topw[t * 2 + k];
        size_t idx = (size_t)slot * (DDIM / 4) + d4;
        float4 a = p0[idx];
        float4 b = p1[idx];
        const float4 bb = ((const float4*)b2)[e * (DDIM / 4) + d4];
        r.x += gw * (a.x + b.x + bb.x);
        r.y += gw * (a.y + b.y + bb.y);
        r.z += gw * (a.z + b.z + bb.z);
        r.w += gw * (a.w + b.w + bb.w);
    }
    ((float4*)out)[i] = r;
}

// ---------------- launch ----------------
extern "C" void kernel_launch(void* const* d_in, const int* in_sizes, int n_in,
                              void* d_out, int out_size) {
    const float* x  = (const float*)d_in[0];
    const float* Wg = (const float*)d_in[1];
    const float* bg = (const float*)d_in[2];
    const float* W1 = (const float*)d_in[3];
    const float* b1 = (const float*)d_in[4];
    const float* W2 = (const float*)d_in[5];
    const float* b2 = (const float*)d_in[6];
    float* out = (float*)d_out;

    zero_kernel<<<1, 32>>>();
    router_kernel<<<T_TOK / 8, 256>>>(x, Wg, bg);
    prefix_kernel<<<1, 1>>>();
    scatter_kernel<<<T_TOK / 256, 256>>>();

    dim3 g1(HDIM / 256, T_TOK / 128, NEXP);          // (16, 64, 8)
    gemm1_kernel<<<g1, 256>>>(x, W1, b1);

    dim3 g2(DDIM / 256, T_TOK / 128, NEXP * NSPLIT); // (4, 64, 16)
    gemm2_kernel<<<g2, 256>>>(W2);

    reduce_kernel<<<(T_TOK * DDIM / 4 + 255) / 256, 256>>>(b2, out);
}

// round 16
// speedup vs baseline: 1.1807x; 1.0087x over previous
#include <cuda_runtime.h>
#include <math.h>
#include <stdint.h>

// Problem constants
#define T_TOK 8192          // B*S tokens
#define DDIM  1024          // model dim
#define NEXP  8             // experts
#define TOPK  2
#define HDIM  4096          // FFN hidden per expert
#define PAIRS (T_TOK * TOPK)
#define NSPLIT 2            // split-K factor for GEMM2
#define KSPL (HDIM / NSPLIT)

// ---------------- device scratch ----------------
__device__ int   g_cnt[NEXP];
__device__ int   g_fill[NEXP];
__device__ int   g_off[NEXP + 1];
__device__ int   g_topi[T_TOK * TOPK];
__device__ float g_topw[T_TOK * TOPK];
__device__ int   g_tok[PAIRS];
__device__ float g_gw[PAIRS];
__device__ int   g_srt[T_TOK * TOPK];                        // (t,k) -> slot
__device__ __align__(16) float g_h[(size_t)PAIRS * HDIM];    // 256 MB intermediate
__device__ __align__(16) float g_p[(size_t)NSPLIT * PAIRS * DDIM];  // 128 MB partials

// ---------------- small kernels ----------------
__global__ void zero_kernel() {
    int i = threadIdx.x;
    if (i < NEXP) { g_cnt[i] = 0; g_fill[i] = 0; }
}

__global__ void router_kernel(const float* __restrict__ x,
                              const float* __restrict__ Wg,
                              const float* __restrict__ bg) {
    int warp = (blockIdx.x * blockDim.x + threadIdx.x) >> 5;
    int lane = threadIdx.x & 31;
    if (warp >= T_TOK) return;
    const float* xr = x + (size_t)warp * DDIM;

    float acc[NEXP];
#pragma unroll
    for (int e = 0; e < NEXP; e++) acc[e] = 0.f;

    for (int d = lane; d < DDIM; d += 32) {
        float xv = xr[d];
        const float4* wg = (const float4*)(Wg + (size_t)d * NEXP);
        float4 w0 = wg[0], w1 = wg[1];
        acc[0] += xv * w0.x; acc[1] += xv * w0.y;
        acc[2] += xv * w0.z; acc[3] += xv * w0.w;
        acc[4] += xv * w1.x; acc[5] += xv * w1.y;
        acc[6] += xv * w1.z; acc[7] += xv * w1.w;
    }
#pragma unroll
    for (int e = 0; e < NEXP; e++) {
#pragma unroll
        for (int o = 16; o > 0; o >>= 1)
            acc[e] += __shfl_xor_sync(0xffffffffu, acc[e], o);
    }
    if (lane == 0) {
        float logit[NEXP];
        float m = -1e30f;
#pragma unroll
        for (int e = 0; e < NEXP; e++) { logit[e] = acc[e] + bg[e]; m = fmaxf(m, logit[e]); }
        float p[NEXP], s = 0.f;
#pragma unroll
        for (int e = 0; e < NEXP; e++) { p[e] = __expf(logit[e] - m); s += p[e]; }
        float inv = 1.f / s;
#pragma unroll
        for (int e = 0; e < NEXP; e++) p[e] *= inv;
        int i1 = 0; float v1 = p[0];
#pragma unroll
        for (int e = 1; e < NEXP; e++) if (p[e] > v1) { v1 = p[e]; i1 = e; }
        int i2 = -1; float v2 = -1.f;
#pragma unroll
        for (int e = 0; e < NEXP; e++) {
            if (e == i1) continue;
            if (p[e] > v2) { v2 = p[e]; i2 = e; }
        }
        g_topi[warp * 2 + 0] = i1; g_topw[warp * 2 + 0] = v1;
        g_topi[warp * 2 + 1] = i2; g_topw[warp * 2 + 1] = v2;
        atomicAdd(&g_cnt[i1], 1);
        atomicAdd(&g_cnt[i2], 1);
    }
}

__global__ void prefix_kernel() {
    if (threadIdx.x == 0) {
        int s = 0;
        g_off[0] = 0;
        for (int e = 0; e < NEXP; e++) { s += g_cnt[e]; g_off[e + 1] = s; }
    }
}

__global__ void scatter_kernel() {
    int t = blockIdx.x * blockDim.x + threadIdx.x;
    if (t >= T_TOK) return;
#pragma unroll
    for (int k = 0; k < TOPK; k++) {
        int e = g_topi[t * 2 + k];
        int pos = atomicAdd(&g_fill[e], 1);
        int slot = g_off[e] + pos;
        g_tok[slot] = t;
        g_gw[slot] = g_topw[t * 2 + k];
        g_srt[t * 2 + k] = slot;
    }
}

__device__ __forceinline__ float gelu_exact(float v) {
    return 0.5f * v * (1.0f + erff(v * 0.70710678118654752f));
}

// ---------------- GEMM1: h = gelu(gather(x) @ W1[e] + b1[e]) ----------------
// CTA tile 128(M) x 256(N), BK=16, 256 threads, 8x16/thread.
// smem exactly 48 KB static. One __syncthreads per 16-deep k-chunk.
__global__ __launch_bounds__(256) void gemm1_kernel(const float* __restrict__ x,
                                                    const float* __restrict__ W1,
                                                    const float* __restrict__ b1) {
    int e = blockIdx.z;
    int n_e = g_cnt[e];
    int row0 = blockIdx.y * 128;
    if (row0 >= n_e) return;
    int col0 = blockIdx.x * 256;
    int base = g_off[e];

    __shared__ __align__(16) float As[2][16][128];   // 16 KB
    __shared__ __align__(16) float Bs[2][16][256];   // 32 KB

    int tid = threadIdx.x;
    int arow = tid >> 1;
    int ak = (tid & 1) * 8;            // k sub-offset: 0 or 8
    int grow = row0 + arow;
    int rc = (grow < n_e) ? grow : (n_e - 1);
    const float* aptr = x + (size_t)g_tok[base + rc] * DDIM + ak;

    int br = tid >> 5;                 // 0..7, also handles row br+8
    int bc = (tid & 31) * 4;
    const float* bptr = W1 + (size_t)e * DDIM * HDIM + (size_t)br * HDIM + col0 + bc;

    int tx = tid & 15, ty = tid >> 4;

    float acc[8][16];
#pragma unroll
    for (int i = 0; i < 8; i++)
#pragma unroll
        for (int j = 0; j < 16; j++) acc[i][j] = 0.f;

    const int KB = DDIM / 16;

    float4 aR0 = *(const float4*)(aptr + 0);
    float4 aR1 = *(const float4*)(aptr + 4);
    float4 bR00 = *(const float4*)bptr;
    float4 bR01 = *(const float4*)(bptr + 128);
    float4 bR10 = *(const float4*)(bptr + (size_t)8 * HDIM);
    float4 bR11 = *(const float4*)(bptr + (size_t)8 * HDIM + 128);
#pragma unroll
    for (int q = 0; q < 4; q++) {
        As[0][ak + q][arow]     = (&aR0.x)[q];
        As[0][ak + 4 + q][arow] = (&aR1.x)[q];
    }
    *(float4*)&Bs[0][br][bc]           = bR00;
    *(float4*)&Bs[0][br][bc + 128]     = bR01;
    *(float4*)&Bs[0][br + 8][bc]       = bR10;
    *(float4*)&Bs[0][br + 8][bc + 128] = bR11;
    aR0  = *(const float4*)(aptr + 16);
    aR1  = *(const float4*)(aptr + 20);
    bR00 = *(const float4*)(bptr + (size_t)16 * HDIM);
    bR01 = *(const float4*)(bptr + (size_t)16 * HDIM + 128);
    bR10 = *(const float4*)(bptr + (size_t)24 * HDIM);
    bR11 = *(const float4*)(bptr + (size_t)24 * HDIM + 128);
    __syncthreads();

    for (int kb = 0; kb < KB; kb++) {
        int buf = kb & 1;
        if (kb + 1 < KB) {
#pragma unroll
            for (int q = 0; q < 4; q++) {
                As[buf ^ 1][ak + q][arow]     = (&aR0.x)[q];
                As[buf ^ 1][ak + 4 + q][arow] = (&aR1.x)[q];
            }
            *(float4*)&Bs[buf ^ 1][br][bc]           = bR00;
            *(float4*)&Bs[buf ^ 1][br][bc + 128]     = bR01;
            *(float4*)&Bs[buf ^ 1][br + 8][bc]       = bR10;
            *(float4*)&Bs[buf ^ 1][br + 8][bc + 128] = bR11;
            if (kb + 2 < KB) {
                int k2 = (kb + 2) * 16;
                aR0  = *(const float4*)(aptr + k2);
                aR1  = *(const float4*)(aptr + k2 + 4);
                bR00 = *(const float4*)(bptr + (size_t)k2 * HDIM);
                bR01 = *(const float4*)(bptr + (size_t)k2 * HDIM + 128);
                bR10 = *(const float4*)(bptr + (size_t)(k2 + 8) * HDIM);
                bR11 = *(const float4*)(bptr + (size_t)(k2 + 8) * HDIM + 128);
            }
        }
#pragma unroll
        for (int kk = 0; kk < 16; kk++) {
            float a[8], b[16];
            *(float4*)(a)     = *(float4*)&As[buf][kk][ty * 8];
            *(float4*)(a + 4) = *(float4*)&As[buf][kk][ty * 8 + 4];
#pragma unroll
            for (int q = 0; q < 4; q++)
                *(float4*)(b + q * 4) = *(float4*)&Bs[buf][kk][tx * 4 + q * 64];
#pragma unroll
            for (int i = 0; i < 8; i++)
#pragma unroll
                for (int j = 0; j < 16; j++) acc[i][j] += a[i] * b[j];
        }
        __syncthreads();
    }

#pragma unroll
    for (int i = 0; i < 8; i++) {
        int r = row0 + ty * 8 + i;
        if (r >= n_e) break;
        size_t slot = (size_t)(base + r);
#pragma unroll
        for (int q = 0; q < 4; q++) {
            int n = col0 + tx * 4 + q * 64;
            const float* bb = b1 + (size_t)e * HDIM + n;
            float4 v;
            v.x = gelu_exact(acc[i][q * 4 + 0] + bb[0]);
            v.y = gelu_exact(acc[i][q * 4 + 1] + bb[1]);
            v.z = gelu_exact(acc[i][q * 4 + 2] + bb[2]);
            v.w = gelu_exact(acc[i][q * 4 + 3] + bb[3]);
            *(float4*)&g_h[slot * HDIM + n] = v;
        }
    }
}

// ---------------- GEMM2 split-K: p[s][slot] = h[:, sK:(s+1)K] @ W2[e][sK:(s+1)K, :] ----------------
__global__ __launch_bounds__(256) void gemm2_kernel(const float* __restrict__ W2) {
    int z = blockIdx.z;
    int e = z >> 1;            // NSPLIT = 2
    int sp = z & 1;
    int n_e = g_cnt[e];
    int row0 = blockIdx.y * 128;
    if (row0 >= n_e) return;
    int col0 = blockIdx.x * 256;
    int base = g_off[e];
    int k0g = sp * KSPL;

    __shared__ __align__(16) float As[2][16][128];
    __shared__ __align__(16) float Bs[2][16][256];

    int tid = threadIdx.x;
    int arow = tid >> 1;
    int ak = (tid & 1) * 8;
    int grow = row0 + arow;
    int rc = (grow < n_e) ? grow : (n_e - 1);
    const float* aptr = g_h + (size_t)(base + rc) * HDIM + k0g + ak;

    int br = tid >> 5;
    int bc = (tid & 31) * 4;
    const float* bptr = W2 + ((size_t)e * HDIM + k0g + br) * DDIM + col0 + bc;

    int tx = tid & 15, ty = tid >> 4;

    float acc[8][16];
#pragma unroll
    for (int i = 0; i < 8; i++)
#pragma unroll
        for (int j = 0; j < 16; j++) acc[i][j] = 0.f;

    const int KB = KSPL / 16;

    float4 aR0 = *(const float4*)(aptr + 0);
    float4 aR1 = *(const float4*)(aptr + 4);
    float4 bR00 = *(const float4*)bptr;
    float4 bR01 = *(const float4*)(bptr + 128);
    float4 bR10 = *(const float4*)(bptr + (size_t)8 * DDIM);
    float4 bR11 = *(const float4*)(bptr + (size_t)8 * DDIM + 128);
#pragma unroll
    for (int q = 0; q < 4; q++) {
        As[0][ak + q][arow]     = (&aR0.x)[q];
        As[0][ak + 4 + q][arow] = (&aR1.x)[q];
    }
    *(float4*)&Bs[0][br][bc]           = bR00;
    *(float4*)&Bs[0][br][bc + 128]     = bR01;
    *(float4*)&Bs[0][br + 8][bc]       = bR10;
    *(float4*)&Bs[0][br + 8][bc + 128] = bR11;
    aR0  = *(const float4*)(aptr + 16);
    aR1  = *(const float4*)(aptr + 20);
    bR00 = *(const float4*)(bptr + (size_t)16 * DDIM);
    bR01 = *(const float4*)(bptr + (size_t)16 * DDIM + 128);
    bR10 = *(const float4*)(bptr + (size_t)24 * DDIM);
    bR11 = *(const float4*)(bptr + (size_t)24 * DDIM + 128);
    __syncthreads();

    for (int kb = 0; kb < KB; kb++) {
        int buf = kb & 1;
        if (kb + 1 < KB) {
#pragma unroll
            for (int q = 0; q < 4; q++) {
                As[buf ^ 1][ak + q][arow]     = (&aR0.x)[q];
                As[buf ^ 1][ak + 4 + q][arow] = (&aR1.x)[q];
            }
            *(float4*)&Bs[buf ^ 1][br][bc]           = bR00;
            *(float4*)&Bs[buf ^ 1][br][bc + 128]     = bR01;
            *(float4*)&Bs[buf ^ 1][br + 8][bc]       = bR10;
            *(float4*)&Bs[buf ^ 1][br + 8][bc + 128] = bR11;
            if (kb + 2 < KB) {
                int k2 = (kb + 2) * 16;
                aR0  = *(const float4*)(aptr + k2);
                aR1  = *(const float4*)(aptr + k2 + 4);
                bR00 = *(const float4*)(bptr + (size_t)k2 * DDIM);
                bR01 = *(const float4*)(bptr + (size_t)k2 * DDIM + 128);
                bR10 = *(const float4*)(bptr + (size_t)(k2 + 8) * DDIM);
                bR11 = *(const float4*)(bptr + (size_t)(k2 + 8) * DDIM + 128);
            }
        }
#pragma unroll
        for (int kk = 0; kk < 16; kk++) {
            float a[8], b[16];
            *(float4*)(a)     = *(float4*)&As[buf][kk][ty * 8];
            *(float4*)(a + 4) = *(float4*)&As[buf][kk][ty * 8 + 4];
#pragma unroll
            for (int q = 0; q < 4; q++)
                *(float4*)(b + q * 4) = *(float4*)&Bs[buf][kk][tx * 4 + q * 64];
#pragma unroll
            for (int i = 0; i < 8; i++)
#pragma unroll
                for (int j = 0; j < 16; j++) acc[i][j] += a[i] * b[j];
        }
        __syncthreads();
    }

    float* pp = g_p + (size_t)sp * PAIRS * DDIM;
#pragma unroll
    for (int i = 0; i < 8; i++) {
        int r = row0 + ty * 8 + i;
        if (r >= n_e) break;
        size_t slot = (size_t)(base + r);
#pragma unroll
        for (int q = 0; q < 4; q++) {
            int n = col0 + tx * 4 + q * 64;
            *(float4*)&pp[slot * DDIM + n] = *(float4*)&acc[i][q * 4];
        }
    }
}

// ---------------- reduce: out[t] = sum_k gw * (sum_s p[s][slot] + b2[e]) ----------------
__global__ void reduce_kernel(const float* __restrict__ b2, float* __restrict__ out) {
    int i = blockIdx.x * blockDim.x + threadIdx.x;   // float4 index
    const int NV = T_TOK * DDIM / 4;
    if (i >= NV) return;
    int t = i / (DDIM / 4);
    int d4 = i % (DDIM / 4);
    const float4* p0 = (const float4*)g_p;
    const float4* p1 = (const float4*)(g_p + (size_t)PAIRS * DDIM);
    float4 r = make_float4(0.f, 0.f, 0.f, 0.f);
#pragma unroll
    for (int k = 0; k < TOPK; k++) {
        int slot = g_srt[t * 2 + k];
        int e = g_topi[t * 2 + k];
        float gw = g_topw[t * 2 + k];
        size_t idx = (size_t)slot * (DDIM / 4) + d4;
        float4 a = p0[idx];
        float4 b = p1[idx];
        const float4 bb = ((const float4*)b2)[e * (DDIM / 4) + d4];
        r.x += gw * (a.x + b.x + bb.x);
        r.y += gw * (a.y + b.y + bb.y);
        r.z += gw * (a.z + b.z + bb.z);
        r.w += gw * (a.w + b.w + bb.w);
    }
    ((float4*)out)[i] = r;
}

// ---------------- launch ----------------
extern "C" void kernel_launch(void* const* d_in, const int* in_sizes, int n_in,
                              void* d_out, int out_size) {
    const float* x  = (const float*)d_in[0];
    const float* Wg = (const float*)d_in[1];
    const float* bg = (const float*)d_in[2];
    const float* W1 = (const float*)d_in[3];
    const float* b1 = (const float*)d_in[4];
    const float* W2 = (const float*)d_in[5];
    const float* b2 = (const float*)d_in[6];
    float* out = (float*)d_out;

    zero_kernel<<<1, 32>>>();
    router_kernel<<<T_TOK / 8, 256>>>(x, Wg, bg);
    prefix_kernel<<<1, 1>>>();
    scatter_kernel<<<T_TOK / 256, 256>>>();

    dim3 g1(HDIM / 256, T_TOK / 128, NEXP);          // (16, 64, 8)
    gemm1_kernel<<<g1, 256>>>(x, W1, b1);

    dim3 g2(DDIM / 256, T_TOK / 128, NEXP * NSPLIT); // (4, 64, 16)
    gemm2_kernel<<<g2, 256>>>(W2);

    reduce_kernel<<<(T_TOK * DDIM / 4 + 255) / 256, 256>>>(b2, out);
}